// round 2
// baseline (speedup 1.0000x reference)
#include <cuda_runtime.h>
#include <cuda_bf16.h>
#include <math.h>

#define SEQ   256
#define INP   4
#define D     128
#define BATCH 2048
#define TB    16

// ---------------- device scratch ----------------
__device__ float g_M[2][D*D];
__device__ float g_la[BATCH];
__device__ float g_logz;

// ---------------- init ----------------
__global__ void init_kernel(const float* __restrict__ edges) {
    int idx = blockIdx.x * blockDim.x + threadIdx.x;
    if (idx < D*D) g_M[0][idx] = edges[idx >> 7] * edges[idx & 127];
    if (idx == 0)  g_logz = 0.f;
}

// ---------------- amplitude scan ----------------
// smem floats: As 128*129 | hb 16*128 | hg 128*28 | rns 16 | logn 16 | ints
#define AS_SZ   (128*129)
#define HB_SZ   (16*128)
#define HG_STR  28
#define HG_SZ   (128*HG_STR)
#define AMP_SMEM_BYTES ((AS_SZ + HB_SZ + HG_SZ + 16 + 16)*4 + 64*4)

__global__ void __launch_bounds__(128) amp_kernel(const int* __restrict__ inp,
                                                  const float* __restrict__ core,
                                                  const float* __restrict__ edges) {
    extern __shared__ float sm[];
    float* As   = sm;
    float* hb   = As + AS_SZ;
    float* hg   = hb + HB_SZ;
    float* rns  = hg + HG_SZ;
    float* logn = rns + 16;
    int*   tok    = (int*)(logn + 16);
    int*   ord    = tok + 16;     // 28 slots
    int*   vstart = ord + 28;     // 4
    int*   vcnt   = vstart + 4;   // 4
    int*   ptot   = vcnt + 4;     // 1

    const int tid  = threadIdx.x;
    const int lane = tid & 31;
    const int w    = tid >> 5;
    const int b0   = blockIdx.x * TB;

    {
        float al = edges[tid];
        #pragma unroll
        for (int b = 0; b < TB; b++) hb[b*D + tid] = al;
    }
    if (tid < TB) { rns[tid] = 1.f; logn[tid] = 0.f; }
    __syncthreads();

    for (int t = 0; t < SEQ; t++) {
        if (tid < TB) tok[tid] = inp[t*BATCH + b0 + tid];
        __syncthreads();
        if (tid == 0) {
            int c[4] = {0,0,0,0};
            for (int b = 0; b < TB; b++) c[tok[b]]++;
            int off = 0, pos[4];
            for (int v = 0; v < 4; v++) {
                vstart[v] = off; vcnt[v] = c[v]; pos[v] = off;
                off += (c[v] + 3) & ~3;
            }
            *ptot = off;
            for (int k = 0; k < off; k++) ord[k] = -1;
            for (int b = 0; b < TB; b++) ord[pos[tok[b]]++] = b;
        }
        __syncthreads();

        const int total = *ptot;
        for (int k = 0; k < total; k++) {
            int b = ord[k];
            hg[tid*HG_STR + k] = (b >= 0) ? hb[b*D + tid] * rns[b] : 0.f;
        }
        __syncthreads();

        for (int v = 0; v < 4; v++) {
            int pc = (vcnt[v] + 3) & ~3;
            if (pc == 0) continue;
            const float4* g4 = (const float4*)(core + (((size_t)t*INP + v) << 14));
            #pragma unroll
            for (int it = 0; it < 32; it++) {
                int idx = it*128 + tid;
                float4 x = g4[idx];
                float* p = &As[(idx >> 5)*129 + ((idx & 31) << 2)];
                p[0]=x.x; p[1]=x.y; p[2]=x.z; p[3]=x.w;
            }
            __syncthreads();
            const int vs = vstart[v];
            const float* arow = &As[tid*129];
            for (int base = vs; base < vs + pc; base += 4) {
                float a0=0.f, a1=0.f, a2=0.f, a3=0.f;
                const float* hcol = &hg[base];
                #pragma unroll 8
                for (int j = 0; j < D; j++) {
                    float a = arow[j];
                    float4 h4 = *(const float4*)&hcol[j*HG_STR];
                    a0 += a*h4.x; a1 += a*h4.y; a2 += a*h4.z; a3 += a*h4.w;
                }
                int s0=ord[base], s1=ord[base+1], s2=ord[base+2], s3=ord[base+3];
                if (s0 >= 0) hb[s0*D + tid] = a0;
                if (s1 >= 0) hb[s1*D + tid] = a1;
                if (s2 >= 0) hb[s2*D + tid] = a2;
                if (s3 >= 0) hb[s3*D + tid] = a3;
            }
            __syncthreads();
        }

        #pragma unroll
        for (int q = 0; q < 4; q++) {
            int b = w*4 + q;
            const float* hp = &hb[b*D];
            float x0=hp[lane], x1=hp[lane+32], x2=hp[lane+64], x3=hp[lane+96];
            float s = x0*x0 + x1*x1 + x2*x2 + x3*x3;
            #pragma unroll
            for (int o = 16; o; o >>= 1) s += __shfl_xor_sync(0xffffffffu, s, o);
            if (lane == 0) { rns[b] = rsqrtf(s); logn[b] += 0.5f*logf(s); }
        }
        __syncthreads();
    }

    // amp = (h/||h||) . omega
    const float* om = edges + D;
    #pragma unroll
    for (int q = 0; q < 4; q++) {
        int b = w*4 + q;
        const float* hp = &hb[b*D];
        float d0 = hp[lane]*om[lane] + hp[lane+32]*om[lane+32]
                 + hp[lane+64]*om[lane+64] + hp[lane+96]*om[lane+96];
        #pragma unroll
        for (int o = 16; o; o >>= 1) d0 += __shfl_xor_sync(0xffffffffu, d0, o);
        if (lane == 0) {
            float amp = d0 * rns[b];
            g_la[b0 + b] = 2.f * (logf(fabsf(amp)) + logn[b]);
        }
    }
}

// ---------------- Z scan: one launch per step ----------------
// smem floats: Ms 128*129 | Arc 128*8 | Ts 4*128*2 | red 32
#define Z_SMEM_BYTES ((128*129 + 128*8 + 1024 + 32)*4)

__global__ void __launch_bounds__(128) z_kernel(const float* __restrict__ core, int t) {
    extern __shared__ float sm[];
    float* Ms  = sm;             // staged M, then reused per-i for A_i
    float* Arc = Ms + 128*129;   // [c][8]
    float* Ts  = Arc + 128*8;    // [(i*128+c)*2 + a]
    float* red = Ts + 1024;

    const int tid = threadIdx.x;
    const int a0  = blockIdx.x * 2;
    const float* src = g_M[t & 1];
    float*       dst = g_M[(t & 1) ^ 1];

    float sq = 0.f;
    const float4* s4 = (const float4*)src;
    #pragma unroll
    for (int it = 0; it < 32; it++) {
        int idx = it*128 + tid;
        float4 x = s4[idx];
        sq += x.x*x.x + x.y*x.y + x.z*x.z + x.w*x.w;
        float* p = &Ms[(idx >> 5)*129 + ((idx & 31) << 2)];
        p[0]=x.x; p[1]=x.y; p[2]=x.z; p[3]=x.w;
    }
    #pragma unroll
    for (int r = 0; r < 8; r++)
        Arc[tid*8 + r] = core[((((size_t)t*INP + (r >> 1))*D) + (a0 + (r & 1)))*D + tid];
    #pragma unroll
    for (int o = 16; o; o >>= 1) sq += __shfl_xor_sync(0xffffffffu, sq, o);
    if ((tid & 31) == 0) red[tid >> 5] = sq;
    __syncthreads();
    float s   = red[0] + red[1] + red[2] + red[3];
    float inv = rsqrtf(s);
    if (blockIdx.x == 0 && tid == 0) g_logz += 0.5f*logf(s);

    // phase 1: T[r][tid] = sum_c A_i[a][c] * Mnorm[c][tid]
    float acc[8] = {0.f,0.f,0.f,0.f,0.f,0.f,0.f,0.f};
    for (int c = 0; c < D; c++) {
        float m = Ms[c*129 + tid];
        float4 p01 = *(const float4*)&Arc[c*8];
        float4 p23 = *(const float4*)&Arc[c*8 + 4];
        acc[0] += p01.x*m; acc[1] += p01.y*m; acc[2] += p01.z*m; acc[3] += p01.w*m;
        acc[4] += p23.x*m; acc[5] += p23.y*m; acc[6] += p23.z*m; acc[7] += p23.w*m;
    }
    #pragma unroll
    for (int r = 0; r < 8; r++)
        Ts[((r >> 1)*D + tid)*2 + (r & 1)] = acc[r] * inv;
    __syncthreads();

    // phase 2: M'[a][tid] = sum_i sum_c T_i[a][c] * A_i[tid][c]
    float m0 = 0.f, m1 = 0.f;
    for (int i = 0; i < 4; i++) {
        const float4* a4 = (const float4*)(core + (((size_t)t*INP + i) << 14));
        #pragma unroll
        for (int it = 0; it < 32; it++) {
            int idx = it*128 + tid;
            float4 x = a4[idx];
            float* p = &Ms[(idx >> 5)*129 + ((idx & 31) << 2)];
            p[0]=x.x; p[1]=x.y; p[2]=x.z; p[3]=x.w;
        }
        __syncthreads();
        const float*  arow = &Ms[tid*129];
        const float2* tp   = (const float2*)&Ts[i*256];
        #pragma unroll 8
        for (int c = 0; c < D; c++) {
            float  a  = arow[c];
            float2 tv = tp[c];
            m0 += tv.x*a; m1 += tv.y*a;
        }
        __syncthreads();
    }
    dst[a0*D + tid]     = m0;
    dst[(a0+1)*D + tid] = m1;
}

// ---------------- final combine ----------------
__global__ void fin_kernel(const float* __restrict__ edges, float* __restrict__ out) {
    __shared__ float red[4];
    __shared__ float lzs;
    const int tid = threadIdx.x;
    const float* om = edges + D;
    const float* M  = g_M[0];   // t=255 wrote parity 0
    float q = 0.f;
    for (int a = 0; a < D; a++) q += om[a] * M[a*D + tid];
    q *= om[tid];
    #pragma unroll
    for (int o = 16; o; o >>= 1) q += __shfl_xor_sync(0xffffffffu, q, o);
    if ((tid & 31) == 0) red[tid >> 5] = q;
    __syncthreads();
    if (tid == 0) lzs = logf(red[0] + red[1] + red[2] + red[3]) + g_logz;
    __syncthreads();
    float logZ = lzs;
    for (int b = tid; b < BATCH; b += 128) out[b] = g_la[b] - logZ;
}

// ---------------- launch ----------------
extern "C" void kernel_launch(void* const* d_in, const int* in_sizes, int n_in,
                              void* d_out, int out_size) {
    const int*   inp   = (const int*)d_in[0];
    const float* core  = (const float*)d_in[1];
    const float* edges = (const float*)d_in[2];
    float*       out   = (float*)d_out;

    cudaFuncSetAttribute(amp_kernel, cudaFuncAttributeMaxDynamicSharedMemorySize, AMP_SMEM_BYTES);
    cudaFuncSetAttribute(z_kernel,   cudaFuncAttributeMaxDynamicSharedMemorySize, Z_SMEM_BYTES);

    init_kernel<<<64, 256>>>(edges);
    amp_kernel<<<BATCH/TB, 128, AMP_SMEM_BYTES>>>(inp, core, edges);
    for (int t = 0; t < SEQ; t++)
        z_kernel<<<64, 128, Z_SMEM_BYTES>>>(core, t);
    fin_kernel<<<1, 128>>>(edges, out);
}

// round 3
// speedup vs baseline: 1.0051x; 1.0051x over previous
#include <cuda_runtime.h>
#include <math.h>

#define SEQ   256
#define INP   4
#define D     128
#define BATCH 2048
#define TB    16
#define ZBLK  64

// ---------------- device scratch ----------------
__device__ float    g_M[2][D*D];
__device__ float    g_la[BATCH];
__device__ float    g_logz;
__device__ unsigned g_bar;

// ---------------- init ----------------
__global__ void init_kernel(const float* __restrict__ edges) {
    int idx = blockIdx.x * blockDim.x + threadIdx.x;
    if (idx < D*D) g_M[0][idx] = edges[idx >> 7] * edges[idx & 127];
    if (idx == 0) { g_logz = 0.f; g_bar = 0u; }
}

// ---------------- amplitude scan (256 threads, split-j teams) ----------------
#define AS_SZ (128*129)
#define AMP_SMEM_FLOATS (AS_SZ + TB*128 + 128*28 + 1024 + 16 + 16)
#define AMP_SMEM_BYTES  (AMP_SMEM_FLOATS*4 + 64*4)

__global__ void __launch_bounds__(256) amp_kernel(const int* __restrict__ inp,
                                                  const float* __restrict__ core,
                                                  const float* __restrict__ edges) {
    extern __shared__ float sm[];
    float* As   = sm;                 // [128][129]
    float* hb   = As + AS_SZ;         // [16][128]
    float* hg   = hb + TB*128;        // [128][28]
    float* pb   = hg + 128*28;        // [2][512] partial-sum buffers
    float* rns  = pb + 1024;          // [16]
    float* logn = rns + 16;           // [16]
    int* tok    = (int*)(logn + 16);  // 16
    int* ord    = tok + 16;           // 28
    int* vstart = ord + 28;           // 4
    int* vcnt   = vstart + 4;         // 4
    int* ptot   = vcnt + 4;           // 1

    const int tid  = threadIdx.x;
    const int row  = tid & 127;
    const int team = tid >> 7;
    const int lane = tid & 31;
    const int w    = tid >> 5;
    const int b0   = blockIdx.x * TB;
    const int jb   = team * 64;

    if (!team) {
        float al = edges[row];
        #pragma unroll
        for (int b = 0; b < TB; b++) hb[b*128 + row] = al;
        if (row < TB) { rns[row] = 1.f; logn[row] = 0.f; }
    }
    __syncthreads();

    int buf = 0;
    for (int t = 0; t < SEQ; t++) {
        if (tid < TB) tok[tid] = inp[t*BATCH + b0 + tid];
        __syncthreads();
        if (tid == 0) {
            int c[4] = {0,0,0,0};
            for (int b = 0; b < TB; b++) c[tok[b]]++;
            int off = 0, pos[4];
            for (int v = 0; v < 4; v++) {
                vstart[v] = off; vcnt[v] = c[v]; pos[v] = off;
                off += (c[v] + 3) & ~3;
            }
            *ptot = off;
            for (int k = 0; k < off; k++) ord[k] = -1;
            for (int b = 0; b < TB; b++) ord[pos[tok[b]]++] = b;
        }
        __syncthreads();

        const int total = *ptot;
        for (int k = team; k < total; k += 2) {
            int b = ord[k];
            hg[row*28 + k] = (b >= 0) ? hb[b*128 + row] * rns[b] : 0.f;
        }
        __syncthreads();

        for (int v = 0; v < 4; v++) {
            int pc = (vcnt[v] + 3) & ~3;
            if (!pc) continue;
            const float4* g4 = (const float4*)(core + (((size_t)t*INP + v) << 14));
            #pragma unroll
            for (int it = 0; it < 16; it++) {
                int idx = it*256 + tid;
                float4 x = g4[idx];
                float* p = &As[(idx >> 5)*129 + ((idx & 31) << 2)];
                p[0]=x.x; p[1]=x.y; p[2]=x.z; p[3]=x.w;
            }
            __syncthreads();
            const int vs = vstart[v];
            const float* arow = &As[row*129 + jb];
            for (int base = vs; base < vs + pc; base += 4) {
                float a0=0.f, a1=0.f, a2=0.f, a3=0.f;
                const float* hcol = &hg[jb*28 + base];
                #pragma unroll 16
                for (int j = 0; j < 64; j++) {
                    float a  = arow[j];
                    float4 h4 = *(const float4*)&hcol[j*28];
                    a0 += a*h4.x; a1 += a*h4.y; a2 += a*h4.z; a3 += a*h4.w;
                }
                float* pp = &pb[buf*512];
                if (team) { pp[row]=a0; pp[128+row]=a1; pp[256+row]=a2; pp[384+row]=a3; }
                __syncthreads();
                if (!team) {
                    a0 += pp[row]; a1 += pp[128+row]; a2 += pp[256+row]; a3 += pp[384+row];
                    int s0=ord[base], s1=ord[base+1], s2=ord[base+2], s3=ord[base+3];
                    if (s0 >= 0) hb[s0*128 + row] = a0;
                    if (s1 >= 0) hb[s1*128 + row] = a1;
                    if (s2 >= 0) hb[s2*128 + row] = a2;
                    if (s3 >= 0) hb[s3*128 + row] = a3;
                }
                buf ^= 1;
            }
        }
        __syncthreads();

        // norms: 8 warps x 2 batches each
        #pragma unroll
        for (int q = 0; q < 2; q++) {
            int b = w*2 + q;
            const float* hp = &hb[b*128];
            float x0=hp[lane], x1=hp[lane+32], x2=hp[lane+64], x3=hp[lane+96];
            float s = x0*x0 + x1*x1 + x2*x2 + x3*x3;
            #pragma unroll
            for (int o = 16; o; o >>= 1) s += __shfl_xor_sync(0xffffffffu, s, o);
            if (!lane) { rns[b] = rsqrtf(s); logn[b] += 0.5f*logf(s); }
        }
        __syncthreads();
    }

    const float* om = edges + D;
    #pragma unroll
    for (int q = 0; q < 2; q++) {
        int b = w*2 + q;
        const float* hp = &hb[b*128];
        float d = hp[lane]*om[lane] + hp[lane+32]*om[lane+32]
                + hp[lane+64]*om[lane+64] + hp[lane+96]*om[lane+96];
        #pragma unroll
        for (int o = 16; o; o >>= 1) d += __shfl_xor_sync(0xffffffffu, d, o);
        if (!lane) g_la[b0 + b] = 2.f*(logf(fabsf(d*rns[b])) + logn[b]);
    }
}

// ---------------- persistent Z scan: ONE launch, software barrier ----------------
#define Z_SMEM_BYTES ((128*129 + 1024 + 1024 + 4)*4)

__global__ void __launch_bounds__(128) zp_kernel(const float* __restrict__ core) {
    extern __shared__ float sm[];
    float* Ms  = sm;              // [128][129]
    float* Arc = Ms + 128*129;    // [128][8]
    float* Ts  = Arc + 1024;      // [(i*128+c)*2 + a]
    float* red = Ts + 1024;       // [4]

    const int tid = threadIdx.x;
    const int a0  = blockIdx.x * 2;
    float lz = 0.f;

    for (int t = 0; t < SEQ; t++) {
        const float* src = g_M[t & 1];
        float*       dst = g_M[(t & 1) ^ 1];

        float sq = 0.f;
        const float4* s4 = (const float4*)src;
        #pragma unroll
        for (int it = 0; it < 32; it++) {
            int idx = it*128 + tid;
            float4 x = __ldcg(&s4[idx]);           // bypass stale L1 across steps
            sq += x.x*x.x + x.y*x.y + x.z*x.z + x.w*x.w;
            float* p = &Ms[(idx >> 5)*129 + ((idx & 31) << 2)];
            p[0]=x.x; p[1]=x.y; p[2]=x.z; p[3]=x.w;
        }
        #pragma unroll
        for (int r = 0; r < 8; r++)
            Arc[tid*8 + r] = core[((((size_t)t*INP + (r >> 1))*D) + (a0 + (r & 1)))*D + tid];
        #pragma unroll
        for (int o = 16; o; o >>= 1) sq += __shfl_xor_sync(0xffffffffu, sq, o);
        if (!(tid & 31)) red[tid >> 5] = sq;
        __syncthreads();
        float s   = red[0] + red[1] + red[2] + red[3];
        float inv = rsqrtf(s);
        if (blockIdx.x == 0 && tid == 0) lz += 0.5f*logf(s);

        // phase 1: T[r][tid] = sum_c A_i[a][c] * (M/||M||)[c][tid]
        float acc[8] = {0,0,0,0,0,0,0,0};
        for (int c = 0; c < D; c++) {
            float  m   = Ms[c*129 + tid];
            float4 p01 = *(const float4*)&Arc[c*8];
            float4 p23 = *(const float4*)&Arc[c*8 + 4];
            acc[0]+=p01.x*m; acc[1]+=p01.y*m; acc[2]+=p01.z*m; acc[3]+=p01.w*m;
            acc[4]+=p23.x*m; acc[5]+=p23.y*m; acc[6]+=p23.z*m; acc[7]+=p23.w*m;
        }
        #pragma unroll
        for (int r = 0; r < 8; r++)
            Ts[((r >> 1)*D + tid)*2 + (r & 1)] = acc[r] * inv;
        __syncthreads();

        // phase 2: M'[a][tid] = sum_i sum_c T_i[a][c] * A_i[tid][c]
        float m0 = 0.f, m1 = 0.f;
        for (int i = 0; i < 4; i++) {
            const float4* a4 = (const float4*)(core + (((size_t)t*INP + i) << 14));
            #pragma unroll
            for (int it = 0; it < 32; it++) {
                int idx = it*128 + tid;
                float4 x = a4[idx];
                float* p = &Ms[(idx >> 5)*129 + ((idx & 31) << 2)];
                p[0]=x.x; p[1]=x.y; p[2]=x.z; p[3]=x.w;
            }
            __syncthreads();
            const float*  arow = &Ms[tid*129];
            const float2* tp   = (const float2*)&Ts[i*256];
            #pragma unroll 8
            for (int c = 0; c < D; c++) {
                float a = arow[c]; float2 tv = tp[c];
                m0 += tv.x*a; m1 += tv.y*a;
            }
            __syncthreads();
        }
        dst[a0*D + tid]     = m0;
        dst[(a0+1)*D + tid] = m1;

        // ---- grid-wide barrier (all 64 blocks co-resident) ----
        __threadfence();
        __syncthreads();
        if (tid == 0) {
            atomicAdd(&g_bar, 1u);
            unsigned need = (unsigned)(t + 1) * ZBLK;
            while (*((volatile unsigned*)&g_bar) < need) {}
        }
        __syncthreads();
    }
    if (blockIdx.x == 0 && tid == 0) g_logz = lz;
}

// ---------------- final combine ----------------
__global__ void fin_kernel(const float* __restrict__ edges, float* __restrict__ out) {
    __shared__ float red[4];
    __shared__ float lzs;
    const int tid = threadIdx.x;
    const float* om = edges + D;
    const float* M  = g_M[0];     // 256 steps even -> final parity 0
    float q = 0.f;
    for (int a = 0; a < D; a++) q += om[a] * M[a*D + tid];
    q *= om[tid];
    #pragma unroll
    for (int o = 16; o; o >>= 1) q += __shfl_xor_sync(0xffffffffu, q, o);
    if (!(tid & 31)) red[tid >> 5] = q;
    __syncthreads();
    if (tid == 0) lzs = logf(red[0] + red[1] + red[2] + red[3]) + g_logz;
    __syncthreads();
    float logZ = lzs;
    for (int b = tid; b < BATCH; b += 128) out[b] = g_la[b] - logZ;
}

// ---------------- launch ----------------
extern "C" void kernel_launch(void* const* d_in, const int* in_sizes, int n_in,
                              void* d_out, int out_size) {
    const int*   inp   = (const int*)d_in[0];
    const float* core  = (const float*)d_in[1];
    const float* edges = (const float*)d_in[2];
    float*       out   = (float*)d_out;

    cudaFuncSetAttribute(amp_kernel, cudaFuncAttributeMaxDynamicSharedMemorySize, AMP_SMEM_BYTES);
    cudaFuncSetAttribute(zp_kernel,  cudaFuncAttributeMaxDynamicSharedMemorySize, Z_SMEM_BYTES);

    init_kernel<<<64, 256>>>(edges);
    amp_kernel<<<BATCH/TB, 256, AMP_SMEM_BYTES>>>(inp, core, edges);
    zp_kernel<<<ZBLK, 128, Z_SMEM_BYTES>>>(core);
    fin_kernel<<<1, 128>>>(edges, out);
}

// round 4
// speedup vs baseline: 1.0066x; 1.0014x over previous
#include <cuda_runtime.h>
#include <math.h>

#define SEQ   256
#define INP   4
#define D     128
#define BATCH 2048
#define TB    16
#define ZBLK  64

// ---------------- device scratch ----------------
__device__ float    g_M[2][D*D];
__device__ float    g_la[BATCH];
__device__ float    g_logz;
__device__ unsigned g_bar;

// ---------------- init ----------------
__global__ void init_kernel(const float* __restrict__ edges) {
    int idx = blockIdx.x * blockDim.x + threadIdx.x;
    if (idx < D*D) g_M[0][idx] = edges[idx >> 7] * edges[idx & 127];
    if (idx == 0) { g_logz = 0.f; g_bar = 0u; }
}

// ---------------- amplitude scan (256 threads, split-j teams) ----------------
#define AS_SZ (128*129)
#define AMP_SMEM_FLOATS (AS_SZ + TB*128 + 128*28 + 1024 + 16 + 16)
#define AMP_SMEM_BYTES  (AMP_SMEM_FLOATS*4 + 64*4)

__global__ void __launch_bounds__(256) amp_kernel(const int* __restrict__ inp,
                                                  const float* __restrict__ core,
                                                  const float* __restrict__ edges) {
    extern __shared__ float sm[];
    float* As   = sm;                 // [128][129]
    float* hb   = As + AS_SZ;         // [16][128]
    float* hg   = hb + TB*128;        // [128][28]
    float* pb   = hg + 128*28;        // [2][512] partial-sum buffers
    float* rns  = pb + 1024;          // [16]
    float* logn = rns + 16;           // [16]
    int* tok    = (int*)(logn + 16);  // 16
    int* ord    = tok + 16;           // 28
    int* vstart = ord + 28;           // 4
    int* vcnt   = vstart + 4;         // 4
    int* ptot   = vcnt + 4;           // 1

    const int tid  = threadIdx.x;
    const int row  = tid & 127;
    const int team = tid >> 7;
    const int lane = tid & 31;
    const int w    = tid >> 5;
    const int b0   = blockIdx.x * TB;
    const int jb   = team * 64;

    if (!team) {
        float al = edges[row];
        #pragma unroll
        for (int b = 0; b < TB; b++) hb[b*128 + row] = al;
        if (row < TB) { rns[row] = 1.f; logn[row] = 0.f; }
    }
    __syncthreads();

    int buf = 0;
    for (int t = 0; t < SEQ; t++) {
        if (tid < TB) tok[tid] = inp[t*BATCH + b0 + tid];
        __syncthreads();
        if (tid == 0) {
            int c[4] = {0,0,0,0};
            for (int b = 0; b < TB; b++) c[tok[b]]++;
            int off = 0, pos[4];
            for (int v = 0; v < 4; v++) {
                vstart[v] = off; vcnt[v] = c[v]; pos[v] = off;
                off += (c[v] + 3) & ~3;
            }
            *ptot = off;
            for (int k = 0; k < off; k++) ord[k] = -1;
            for (int b = 0; b < TB; b++) ord[pos[tok[b]]++] = b;
        }
        __syncthreads();

        const int total = *ptot;
        for (int k = team; k < total; k += 2) {
            int b = ord[k];
            hg[row*28 + k] = (b >= 0) ? hb[b*128 + row] * rns[b] : 0.f;
        }
        __syncthreads();

        for (int v = 0; v < 4; v++) {
            int pc = (vcnt[v] + 3) & ~3;
            if (!pc) continue;
            const float4* g4 = (const float4*)(core + (((size_t)t*INP + v) << 14));
            #pragma unroll
            for (int it = 0; it < 16; it++) {
                int idx = it*256 + tid;
                float4 x = g4[idx];
                float* p = &As[(idx >> 5)*129 + ((idx & 31) << 2)];
                p[0]=x.x; p[1]=x.y; p[2]=x.z; p[3]=x.w;
            }
            __syncthreads();
            const int vs = vstart[v];
            const float* arow = &As[row*129 + jb];
            for (int base = vs; base < vs + pc; base += 4) {
                float a0=0.f, a1=0.f, a2=0.f, a3=0.f;
                const float* hcol = &hg[jb*28 + base];
                #pragma unroll 16
                for (int j = 0; j < 64; j++) {
                    float a  = arow[j];
                    float4 h4 = *(const float4*)&hcol[j*28];
                    a0 += a*h4.x; a1 += a*h4.y; a2 += a*h4.z; a3 += a*h4.w;
                }
                float* pp = &pb[buf*512];
                if (team) { pp[row]=a0; pp[128+row]=a1; pp[256+row]=a2; pp[384+row]=a3; }
                __syncthreads();
                if (!team) {
                    a0 += pp[row]; a1 += pp[128+row]; a2 += pp[256+row]; a3 += pp[384+row];
                    int s0=ord[base], s1=ord[base+1], s2=ord[base+2], s3=ord[base+3];
                    if (s0 >= 0) hb[s0*128 + row] = a0;
                    if (s1 >= 0) hb[s1*128 + row] = a1;
                    if (s2 >= 0) hb[s2*128 + row] = a2;
                    if (s3 >= 0) hb[s3*128 + row] = a3;
                }
                buf ^= 1;
            }
        }
        __syncthreads();

        // norms: 8 warps x 2 batches each
        #pragma unroll
        for (int q = 0; q < 2; q++) {
            int b = w*2 + q;
            const float* hp = &hb[b*128];
            float x0=hp[lane], x1=hp[lane+32], x2=hp[lane+64], x3=hp[lane+96];
            float s = x0*x0 + x1*x1 + x2*x2 + x3*x3;
            #pragma unroll
            for (int o = 16; o; o >>= 1) s += __shfl_xor_sync(0xffffffffu, s, o);
            if (!lane) { rns[b] = rsqrtf(s); logn[b] += 0.5f*logf(s); }
        }
        __syncthreads();
    }

    const float* om = edges + D;
    #pragma unroll
    for (int q = 0; q < 2; q++) {
        int b = w*2 + q;
        const float* hp = &hb[b*128];
        float d = hp[lane]*om[lane] + hp[lane+32]*om[lane+32]
                + hp[lane+64]*om[lane+64] + hp[lane+96]*om[lane+96];
        #pragma unroll
        for (int o = 16; o; o >>= 1) d += __shfl_xor_sync(0xffffffffu, d, o);
        if (!lane) g_la[b0 + b] = 2.f*(logf(fabsf(d*rns[b])) + logn[b]);
    }
}

// ---------------- persistent Z scan: ONE launch, software barrier ----------------
#define Z_SMEM_BYTES ((128*129 + 1024 + 1024 + 4)*4)

__global__ void __launch_bounds__(128) zp_kernel(const float* __restrict__ core) {
    extern __shared__ float sm[];
    float* Ms  = sm;              // [128][129]
    float* Arc = Ms + 128*129;    // [128][8]
    float* Ts  = Arc + 1024;      // [(i*128+c)*2 + a]
    float* red = Ts + 1024;       // [4]

    const int tid = threadIdx.x;
    const int a0  = blockIdx.x * 2;
    float lz = 0.f;

    for (int t = 0; t < SEQ; t++) {
        const float* src = g_M[t & 1];
        float*       dst = g_M[(t & 1) ^ 1];

        float sq = 0.f;
        const float4* s4 = (const float4*)src;
        #pragma unroll
        for (int it = 0; it < 32; it++) {
            int idx = it*128 + tid;
            float4 x = __ldcg(&s4[idx]);           // bypass stale L1 across steps
            sq += x.x*x.x + x.y*x.y + x.z*x.z + x.w*x.w;
            float* p = &Ms[(idx >> 5)*129 + ((idx & 31) << 2)];
            p[0]=x.x; p[1]=x.y; p[2]=x.z; p[3]=x.w;
        }
        #pragma unroll
        for (int r = 0; r < 8; r++)
            Arc[tid*8 + r] = core[((((size_t)t*INP + (r >> 1))*D) + (a0 + (r & 1)))*D + tid];
        #pragma unroll
        for (int o = 16; o; o >>= 1) sq += __shfl_xor_sync(0xffffffffu, sq, o);
        if (!(tid & 31)) red[tid >> 5] = sq;
        __syncthreads();
        float s   = red[0] + red[1] + red[2] + red[3];
        float inv = rsqrtf(s);
        if (blockIdx.x == 0 && tid == 0) lz += 0.5f*logf(s);

        // phase 1: T[r][tid] = sum_c A_i[a][c] * (M/||M||)[c][tid]
        float acc[8] = {0,0,0,0,0,0,0,0};
        for (int c = 0; c < D; c++) {
            float  m   = Ms[c*129 + tid];
            float4 p01 = *(const float4*)&Arc[c*8];
            float4 p23 = *(const float4*)&Arc[c*8 + 4];
            acc[0]+=p01.x*m; acc[1]+=p01.y*m; acc[2]+=p01.z*m; acc[3]+=p01.w*m;
            acc[4]+=p23.x*m; acc[5]+=p23.y*m; acc[6]+=p23.z*m; acc[7]+=p23.w*m;
        }
        #pragma unroll
        for (int r = 0; r < 8; r++)
            Ts[((r >> 1)*D + tid)*2 + (r & 1)] = acc[r] * inv;
        __syncthreads();

        // phase 2: M'[a][tid] = sum_i sum_c T_i[a][c] * A_i[tid][c]
        float m0 = 0.f, m1 = 0.f;
        for (int i = 0; i < 4; i++) {
            const float4* a4 = (const float4*)(core + (((size_t)t*INP + i) << 14));
            #pragma unroll
            for (int it = 0; it < 32; it++) {
                int idx = it*128 + tid;
                float4 x = a4[idx];
                float* p = &Ms[(idx >> 5)*129 + ((idx & 31) << 2)];
                p[0]=x.x; p[1]=x.y; p[2]=x.z; p[3]=x.w;
            }
            __syncthreads();
            const float*  arow = &Ms[tid*129];
            const float2* tp   = (const float2*)&Ts[i*256];
            #pragma unroll 8
            for (int c = 0; c < D; c++) {
                float a = arow[c]; float2 tv = tp[c];
                m0 += tv.x*a; m1 += tv.y*a;
            }
            __syncthreads();
        }
        dst[a0*D + tid]     = m0;
        dst[(a0+1)*D + tid] = m1;

        // ---- grid-wide barrier (all 64 blocks co-resident) ----
        __threadfence();
        __syncthreads();
        if (tid == 0) {
            atomicAdd(&g_bar, 1u);
            unsigned need = (unsigned)(t + 1) * ZBLK;
            while (*((volatile unsigned*)&g_bar) < need) {}
        }
        __syncthreads();
    }
    if (blockIdx.x == 0 && tid == 0) g_logz = lz;
}

// ---------------- final combine ----------------
__global__ void fin_kernel(const float* __restrict__ edges, float* __restrict__ out) {
    __shared__ float red[4];
    __shared__ float lzs;
    const int tid = threadIdx.x;
    const float* om = edges + D;
    const float* M  = g_M[0];     // 256 steps even -> final parity 0
    float q = 0.f;
    for (int a = 0; a < D; a++) q += om[a] * M[a*D + tid];
    q *= om[tid];
    #pragma unroll
    for (int o = 16; o; o >>= 1) q += __shfl_xor_sync(0xffffffffu, q, o);
    if (!(tid & 31)) red[tid >> 5] = q;
    __syncthreads();
    if (tid == 0) lzs = logf(red[0] + red[1] + red[2] + red[3]) + g_logz;
    __syncthreads();
    float logZ = lzs;
    for (int b = tid; b < BATCH; b += 128) out[b] = g_la[b] - logZ;
}

// ---------------- launch ----------------
extern "C" void kernel_launch(void* const* d_in, const int* in_sizes, int n_in,
                              void* d_out, int out_size) {
    const int*   inp   = (const int*)d_in[0];
    const float* core  = (const float*)d_in[1];
    const float* edges = (const float*)d_in[2];
    float*       out   = (float*)d_out;

    cudaFuncSetAttribute(amp_kernel, cudaFuncAttributeMaxDynamicSharedMemorySize, AMP_SMEM_BYTES);
    cudaFuncSetAttribute(zp_kernel,  cudaFuncAttributeMaxDynamicSharedMemorySize, Z_SMEM_BYTES);

    init_kernel<<<64, 256>>>(edges);
    amp_kernel<<<BATCH/TB, 256, AMP_SMEM_BYTES>>>(inp, core, edges);
    zp_kernel<<<ZBLK, 128, Z_SMEM_BYTES>>>(core);
    fin_kernel<<<1, 128>>>(edges, out);
}